// round 8
// baseline (speedup 1.0000x reference)
#include <cuda_runtime.h>
#include <cuda_fp16.h>

#define N_NODES 4096
#define FIN     128
#define NH      4
#define FOUT    64
#define HF      256
#define MAXD    256
#define NBLK    1024   // even b -> GEMM (512), odd b -> scan (512)

// -------- device scratch --------
__device__ __half g_h2[NH * N_NODES * FOUT];     // fp16 [h][n][f] (2 MB), 128B per (h,n)
__device__ float  g_ss[N_NODES * NH];            // src score [n][h]
__device__ float  g_st[N_NODES * NH];            // tgt score [n][h]
__device__ float  g_skip[N_NODES * HF];          // skip proj result
__device__ unsigned short g_adj[(size_t)N_NODES * MAXD];
__device__ int    g_deg[N_NODES];

// ============================================================
// Fat kernel. Even blocks: fused tiled GEMM C[4096][512]
//   col-tiles 0..3 = proj heads (+ fused score reductions),
//   col-tiles 4..7 = skip projection.
// Odd blocks: mask scan (warp per row).
// ============================================================
__global__ __launch_bounds__(256) void prep_kernel(
    const float* __restrict__ x,
    const float* __restrict__ mask,
    const float* __restrict__ proj,
    const float* __restrict__ score_src,
    const float* __restrict__ score_tgt,
    const float* __restrict__ skip_w)
{
    __shared__ float xs[64 * 33];
    __shared__ float ws[32 * 68];

    const int b   = blockIdx.x;
    const int tid = threadIdx.x;

    if (b & 1) {
        // ---------------- scan role ----------------
        const int sb   = b >> 1;
        const int wid  = tid >> 5;
        const int lane = tid & 31;
        const int row  = sb * 8 + wid;
        const float4* mr = (const float4*)(mask + (size_t)row * N_NODES);
        unsigned short* adj = g_adj + (size_t)row * MAXD;
        const unsigned lt = (1u << lane) - 1u;
        int base = 0;
#pragma unroll 8
        for (int g = 0; g < N_NODES / 128; g++) {
            const float4 v = mr[g * 32 + lane];
            const unsigned b0 = __ballot_sync(0xffffffffu, v.x == 0.f);
            const unsigned b1 = __ballot_sync(0xffffffffu, v.y == 0.f);
            const unsigned b2 = __ballot_sync(0xffffffffu, v.z == 0.f);
            const unsigned b3 = __ballot_sync(0xffffffffu, v.w == 0.f);
            const int c0 = __popc(b0), c1 = __popc(b1), c2 = __popc(b2), c3 = __popc(b3);
            const int e0 = g * 128 + lane * 4;
            if (v.x == 0.f) { int p = base + __popc(b0 & lt);                if (p < MAXD) adj[p] = (unsigned short)(e0);     }
            if (v.y == 0.f) { int p = base + c0 + __popc(b1 & lt);           if (p < MAXD) adj[p] = (unsigned short)(e0 + 1); }
            if (v.z == 0.f) { int p = base + c0 + c1 + __popc(b2 & lt);      if (p < MAXD) adj[p] = (unsigned short)(e0 + 2); }
            if (v.w == 0.f) { int p = base + c0 + c1 + c2 + __popc(b3 & lt); if (p < MAXD) adj[p] = (unsigned short)(e0 + 3); }
            base += c0 + c1 + c2 + c3;
        }
        if (lane == 0) g_deg[row] = min(base, MAXD);
        return;
    }

    // ---------------- GEMM role ----------------
    const int gb = b >> 1;
    const int rt = gb >> 3;
    const int ct = gb & 7;
    const int r0 = rt * 64;
    const int tc = tid & 15;
    const int tr = tid >> 4;

    float acc[4][4];
#pragma unroll
    for (int i = 0; i < 4; i++)
#pragma unroll
        for (int j = 0; j < 4; j++) acc[i][j] = 0.f;

    for (int kt = 0; kt < 4; kt++) {
        const int k0 = kt * 32;
#pragma unroll
        for (int i2 = 0; i2 < 2; i2++) {
            const int idx4 = tid + i2 * 256;
            const int rr = idx4 >> 3, kq = idx4 & 7;
            const float4 v = *(const float4*)(x + (size_t)(r0 + rr) * FIN + k0 + kq * 4);
            float* d = xs + rr * 33 + kq * 4;
            d[0] = v.x; d[1] = v.y; d[2] = v.z; d[3] = v.w;
        }
        if (ct < 4) {
#pragma unroll
            for (int i2 = 0; i2 < 2; i2++) {
                const int idx4 = tid + i2 * 256;
                const int kk = idx4 >> 4, fq = idx4 & 15;
                const float4 v = *(const float4*)(proj + (size_t)ct * FIN * FOUT + (size_t)(k0 + kk) * FOUT + fq * 4);
                *(float4*)(ws + kk * 68 + fq * 4) = v;
            }
        } else {
            const int c0 = (ct - 4) * 64;
#pragma unroll
            for (int i2 = 0; i2 < 2; i2++) {
                const int idx4 = tid + i2 * 256;
                const int cc = idx4 >> 3, kq = idx4 & 7;
                const float4 v = *(const float4*)(skip_w + (size_t)(c0 + cc) * FIN + k0 + kq * 4);
                ws[(kq * 4 + 0) * 68 + cc] = v.x;
                ws[(kq * 4 + 1) * 68 + cc] = v.y;
                ws[(kq * 4 + 2) * 68 + cc] = v.z;
                ws[(kq * 4 + 3) * 68 + cc] = v.w;
            }
        }
        __syncthreads();
#pragma unroll
        for (int k = 0; k < 32; k++) {
            const float4 wv = *(const float4*)(ws + k * 68 + tc * 4);
            const float x0 = xs[(tr * 4 + 0) * 33 + k];
            const float x1 = xs[(tr * 4 + 1) * 33 + k];
            const float x2 = xs[(tr * 4 + 2) * 33 + k];
            const float x3 = xs[(tr * 4 + 3) * 33 + k];
            acc[0][0] = fmaf(x0, wv.x, acc[0][0]); acc[0][1] = fmaf(x0, wv.y, acc[0][1]);
            acc[0][2] = fmaf(x0, wv.z, acc[0][2]); acc[0][3] = fmaf(x0, wv.w, acc[0][3]);
            acc[1][0] = fmaf(x1, wv.x, acc[1][0]); acc[1][1] = fmaf(x1, wv.y, acc[1][1]);
            acc[1][2] = fmaf(x1, wv.z, acc[1][2]); acc[1][3] = fmaf(x1, wv.w, acc[1][3]);
            acc[2][0] = fmaf(x2, wv.x, acc[2][0]); acc[2][1] = fmaf(x2, wv.y, acc[2][1]);
            acc[2][2] = fmaf(x2, wv.z, acc[2][2]); acc[2][3] = fmaf(x2, wv.w, acc[2][3]);
            acc[3][0] = fmaf(x3, wv.x, acc[3][0]); acc[3][1] = fmaf(x3, wv.y, acc[3][1]);
            acc[3][2] = fmaf(x3, wv.z, acc[3][2]); acc[3][3] = fmaf(x3, wv.w, acc[3][3]);
        }
        __syncthreads();
    }

    if (ct < 4) {
        const int h = ct;
        const float4 sv = *(const float4*)(score_src + h * FOUT + tc * 4);
        const float4 tv = *(const float4*)(score_tgt + h * FOUT + tc * 4);
        float pS[4], pT[4];
#pragma unroll
        for (int i = 0; i < 4; i++) {
            const int r = r0 + tr * 4 + i;
            const __half2 h01 = __floats2half2_rn(acc[i][0], acc[i][1]);
            const __half2 h23 = __floats2half2_rn(acc[i][2], acc[i][3]);
            uint2 pk;
            pk.x = *(const unsigned*)&h01;
            pk.y = *(const unsigned*)&h23;
            *(uint2*)((char*)g_h2 + (((size_t)h * N_NODES + r) * FOUT + tc * 4) * 2) = pk;
            pS[i] = acc[i][0] * sv.x + acc[i][1] * sv.y + acc[i][2] * sv.z + acc[i][3] * sv.w;
            pT[i] = acc[i][0] * tv.x + acc[i][1] * tv.y + acc[i][2] * tv.z + acc[i][3] * tv.w;
        }
#pragma unroll
        for (int o = 1; o < 16; o <<= 1) {
#pragma unroll
            for (int i = 0; i < 4; i++) {
                pS[i] += __shfl_xor_sync(0xffffffffu, pS[i], o);
                pT[i] += __shfl_xor_sync(0xffffffffu, pT[i], o);
            }
        }
        if (tc == 0) {
#pragma unroll
            for (int i = 0; i < 4; i++) {
                const int r = r0 + tr * 4 + i;
                g_ss[r * NH + h] = pS[i];
                g_st[r * NH + h] = pT[i];
            }
        }
    } else {
        const int c0 = (ct - 4) * 64;
#pragma unroll
        for (int i = 0; i < 4; i++) {
            const int r = r0 + tr * 4 + i;
            const float4 val = {acc[i][0], acc[i][1], acc[i][2], acc[i][3]};
            *(float4*)(g_skip + (size_t)r * HF + c0 + tc * 4) = val;
        }
    }
}

// ============================================================
// Attention: one warp per (row, head). No smem, no __syncthreads.
// Block = 512 threads = 16 warps = 4 rows x 4 heads.
// Round r covers j in [32r, 32r+32); lanes past deg carry e=0.
// Gather: 4 j's per iter, 8 lanes x uint4(8 halves) per j;
// p/offset broadcast via shfl.idx.
// ============================================================
__global__ __launch_bounds__(512) void attn_kernel(
    const float* __restrict__ bias,
    float* __restrict__ out)
{
    const int wid  = threadIdx.x >> 5;
    const int lane = threadIdx.x & 31;
    const int n    = blockIdx.x * 4 + (wid >> 2);
    const int h    = wid & 3;

    const int deg = g_deg[n];
    const unsigned short* adj = g_adj + (size_t)n * MAXD;
    const float ssv = g_ss[n * NH + h];

    // ---- scores: e[r], byte-offset off[r] per round ----
    float e[8];
    int   off[8];
    float S = 0.f;
#pragma unroll
    for (int r = 0; r < 8; r++) {
        e[r] = 0.f; off[r] = 0;
        if (r * 32 < deg) {                      // warp-uniform
            const int j = r * 32 + lane;
            if (j < deg) {
                const int m = adj[j];
                float v = ssv + g_st[m * NH + h];
                v = v > 0.f ? v : 0.2f * v;
                e[r]   = __expf(v);
                off[r] = m * (FOUT * 2);         // 128 bytes per (h,n) row
            }
        }
        S += e[r];
    }
#pragma unroll
    for (int o = 16; o; o >>= 1) S += __shfl_xor_sync(0xffffffffu, S, o);

    // ---- gather-aggregate ----
    const char* hb = (const char*)g_h2 + (size_t)h * N_NODES * (FOUT * 2);
    const int jq = lane >> 3;        // which of 4 j's this lane serves
    const int fo = (lane & 7) * 16;  // byte offset of this lane's 8 halves
    float a0 = 0.f, a1 = 0.f, a2 = 0.f, a3 = 0.f;
    float a4 = 0.f, a5 = 0.f, a6 = 0.f, a7 = 0.f;

#pragma unroll
    for (int r = 0; r < 8; r++) {
        if (r * 32 >= deg) break;                // warp-uniform
        const float er  = e[r];
        const int   ofr = off[r];
#pragma unroll
        for (int jb = 0; jb < 32; jb += 4) {
            const int   src = jb + jq;
            const float p   = __shfl_sync(0xffffffffu, er, src);
            const int   o4  = __shfl_sync(0xffffffffu, ofr, src);
            const uint4 hv  = *(const uint4*)(hb + o4 + fo);
            const float2 f0 = __half22float2(*(const __half2*)&hv.x);
            const float2 f1 = __half22float2(*(const __half2*)&hv.y);
            const float2 f2 = __half22float2(*(const __half2*)&hv.z);
            const float2 f3 = __half22float2(*(const __half2*)&hv.w);
            a0 = fmaf(p, f0.x, a0); a1 = fmaf(p, f0.y, a1);
            a2 = fmaf(p, f1.x, a2); a3 = fmaf(p, f1.y, a3);
            a4 = fmaf(p, f2.x, a4); a5 = fmaf(p, f2.y, a5);
            a6 = fmaf(p, f3.x, a6); a7 = fmaf(p, f3.y, a7);
        }
    }

    // reduce across the 4 jq groups (lanes differing in bits 3,4)
#pragma unroll
    for (int o = 8; o <= 16; o <<= 1) {
        a0 += __shfl_xor_sync(0xffffffffu, a0, o);
        a1 += __shfl_xor_sync(0xffffffffu, a1, o);
        a2 += __shfl_xor_sync(0xffffffffu, a2, o);
        a3 += __shfl_xor_sync(0xffffffffu, a3, o);
        a4 += __shfl_xor_sync(0xffffffffu, a4, o);
        a5 += __shfl_xor_sync(0xffffffffu, a5, o);
        a6 += __shfl_xor_sync(0xffffffffu, a6, o);
        a7 += __shfl_xor_sync(0xffffffffu, a7, o);
    }

    if (lane < 8) {
        const float inv = 1.f / S;
        const int cbase = h * FOUT + lane * 8;
        const float4 sk0 = *(const float4*)(g_skip + (size_t)n * HF + cbase);
        const float4 sk1 = *(const float4*)(g_skip + (size_t)n * HF + cbase + 4);
        const float4 bi0 = *(const float4*)(bias + cbase);
        const float4 bi1 = *(const float4*)(bias + cbase + 4);
        float o0 = a0 * inv + sk0.x + bi0.x;
        float o1 = a1 * inv + sk0.y + bi0.y;
        float o2 = a2 * inv + sk0.z + bi0.z;
        float o3 = a3 * inv + sk0.w + bi0.w;
        float o4 = a4 * inv + sk1.x + bi1.x;
        float o5 = a5 * inv + sk1.y + bi1.y;
        float o6 = a6 * inv + sk1.z + bi1.z;
        float o7 = a7 * inv + sk1.w + bi1.w;
        o0 = o0 > 0.f ? o0 : (__expf(o0) - 1.f);
        o1 = o1 > 0.f ? o1 : (__expf(o1) - 1.f);
        o2 = o2 > 0.f ? o2 : (__expf(o2) - 1.f);
        o3 = o3 > 0.f ? o3 : (__expf(o3) - 1.f);
        o4 = o4 > 0.f ? o4 : (__expf(o4) - 1.f);
        o5 = o5 > 0.f ? o5 : (__expf(o5) - 1.f);
        o6 = o6 > 0.f ? o6 : (__expf(o6) - 1.f);
        o7 = o7 > 0.f ? o7 : (__expf(o7) - 1.f);
        float* op = out + (size_t)n * HF + cbase;
        *(float4*)op       = make_float4(o0, o1, o2, o3);
        *(float4*)(op + 4) = make_float4(o4, o5, o6, o7);
    }
}

// ============================================================
extern "C" void kernel_launch(void* const* d_in, const int* in_sizes, int n_in,
                              void* d_out, int out_size)
{
    const float* x         = (const float*)d_in[0];
    const float* mask      = (const float*)d_in[1];
    const float* proj      = (const float*)d_in[2];
    const float* score_src = (const float*)d_in[3];
    const float* score_tgt = (const float*)d_in[4];
    const float* skip_w    = (const float*)d_in[5];
    const float* bias      = (const float*)d_in[6];
    float* out             = (float*)d_out;

    prep_kernel<<<NBLK, 256>>>(x, mask, proj, score_src, score_tgt, skip_w);
    attn_kernel<<<N_NODES / 4, 512>>>(bias, out);
}

// round 10
// speedup vs baseline: 1.1707x; 1.1707x over previous
#include <cuda_runtime.h>
#include <cuda_fp16.h>

#define N_NODES 4096
#define FIN     128
#define NH      4
#define FOUT    64
#define HF      256
#define MAXD    256
#define NBLK    1536   // b%3 in {0,1} -> scan (1024 blocks), b%3==2 -> GEMM (512)

// -------- device scratch --------
__device__ float g_h[NH * N_NODES * FOUT];       // fp32 [h][n][f] (4 MB)
__device__ float g_ss[N_NODES * NH];             // src score [n][h]
__device__ float g_st[N_NODES * NH];             // tgt score [n][h] (float4-loadable)
__device__ float g_skip[N_NODES * HF];           // skip proj result
__device__ unsigned short g_adj[(size_t)N_NODES * MAXD];
__device__ int   g_deg[N_NODES];

static __device__ __forceinline__ unsigned pack_half2(float a, float b) {
    const __half2 h = __floats2half2_rn(a, b);
    return *(const unsigned*)&h;
}

// ============================================================
// Fat kernel. b%3==2: tensor-core GEMM tile 64 rows x 64 cols of
// C[4096][512] (col-tiles 0..3 = proj heads + fused scores,
// 4..7 = skip). Else: mask scan, warp per row (4 rows/block).
// ============================================================
__global__ __launch_bounds__(128) void prep_kernel(
    const float* __restrict__ x,
    const float* __restrict__ mask,
    const float* __restrict__ proj,
    const float* __restrict__ score_src,
    const float* __restrict__ score_tgt,
    const float* __restrict__ skip_w)
{
    __shared__ uint4 xs4[64 * 16];   // A tile: 64 rows x 128 halves, swizzled (16 KB)
    __shared__ uint4 ws4[64 * 16];   // B tile: 64 cols x 128 halves, swizzled (16 KB)
    __shared__ float redS[2][64], redT[2][64];

    const int b   = blockIdx.x;
    const int tid = threadIdx.x;

    if (b % 3 != 2) {
        // ---------------- scan role: warp per row ----------------
        const int sb   = (b / 3) * 2 + (b % 3);    // 0..1023
        const int wid  = tid >> 5;
        const int lane = tid & 31;
        const int row  = sb * 4 + wid;
        const float4* mr = (const float4*)(mask + (size_t)row * N_NODES);
        unsigned short* adj = g_adj + (size_t)row * MAXD;
        const unsigned lt = (1u << lane) - 1u;
        int base = 0;
#pragma unroll 8
        for (int g = 0; g < N_NODES / 128; g++) {
            const float4 v = mr[g * 32 + lane];
            const unsigned b0 = __ballot_sync(0xffffffffu, v.x == 0.f);
            const unsigned b1 = __ballot_sync(0xffffffffu, v.y == 0.f);
            const unsigned b2 = __ballot_sync(0xffffffffu, v.z == 0.f);
            const unsigned b3 = __ballot_sync(0xffffffffu, v.w == 0.f);
            const int c0 = __popc(b0), c1 = __popc(b1), c2 = __popc(b2), c3 = __popc(b3);
            const int e0 = g * 128 + lane * 4;
            if (v.x == 0.f) { int p = base + __popc(b0 & lt);                if (p < MAXD) adj[p] = (unsigned short)(e0);     }
            if (v.y == 0.f) { int p = base + c0 + __popc(b1 & lt);           if (p < MAXD) adj[p] = (unsigned short)(e0 + 1); }
            if (v.z == 0.f) { int p = base + c0 + c1 + __popc(b2 & lt);      if (p < MAXD) adj[p] = (unsigned short)(e0 + 2); }
            if (v.w == 0.f) { int p = base + c0 + c1 + c2 + __popc(b3 & lt); if (p < MAXD) adj[p] = (unsigned short)(e0 + 3); }
            base += c0 + c1 + c2 + c3;
        }
        if (lane == 0) g_deg[row] = min(base, MAXD);
        return;
    }

    // ---------------- GEMM role ----------------
    const int gb = b / 3;            // 0..511
    const int rt = gb >> 3;          // row tile 0..63
    const int ct = gb & 7;           // col tile 0..7
    const int r0 = rt * 64;
    const int w    = tid >> 5;       // warp 0..3
    const int lane = tid & 31;
    const int wr = (w >> 1) * 32;    // warp row offset in tile
    const int wc = (w & 1) * 32;     // warp col offset in tile

    // ---- stage A: x[r0..r0+64][0..128] fp32 -> fp16 swizzled ----
    {
        const float4* xg = (const float4*)(x + (size_t)r0 * FIN);
#pragma unroll
        for (int i = 0; i < 8; i++) {
            const int idx = tid + i * 128;      // chunk 0..1023 (16B chunks of 8 halves)
            const int r = idx >> 4, c8 = idx & 15;
            const float4 v0 = xg[r * 32 + c8 * 2];
            const float4 v1 = xg[r * 32 + c8 * 2 + 1];
            uint4 pk;
            pk.x = pack_half2(v0.x, v0.y);
            pk.y = pack_half2(v0.z, v0.w);
            pk.z = pack_half2(v1.x, v1.y);
            pk.w = pack_half2(v1.z, v1.w);
            xs4[r * 16 + (c8 ^ (r & 7))] = pk;
        }
    }
    // ---- stage B: 64 cols x 128 k, layout [c][k] fp16 swizzled ----
    if (ct >= 4) {
        // skip_w rows are already [c][k]
        const float4* wg = (const float4*)(skip_w + (size_t)((ct - 4) * 64) * FIN);
#pragma unroll
        for (int i = 0; i < 8; i++) {
            const int idx = tid + i * 128;
            const int r = idx >> 4, c8 = idx & 15;
            const float4 v0 = wg[r * 32 + c8 * 2];
            const float4 v1 = wg[r * 32 + c8 * 2 + 1];
            uint4 pk;
            pk.x = pack_half2(v0.x, v0.y);
            pk.y = pack_half2(v0.z, v0.w);
            pk.z = pack_half2(v1.x, v1.y);
            pk.w = pack_half2(v1.z, v1.w);
            ws4[r * 16 + (c8 ^ (r & 7))] = pk;
        }
    } else {
        // proj[ct][k][f] -> ws[c=f][k] (transpose during staging)
        const float4* pg = (const float4*)(proj + (size_t)ct * FIN * FOUT);
        __half* wsh = (__half*)ws4;
#pragma unroll
        for (int i = 0; i < 16; i++) {
            const int idx4 = tid + i * 128;     // 0..2047 float4s
            const int k = idx4 >> 4, fq = idx4 & 15;
            const float4 v = pg[k * 16 + fq];
            const int kc = k >> 3, ki = k & 7;
#pragma unroll
            for (int j = 0; j < 4; j++) {
                const int c = fq * 4 + j;
                const float val = (j == 0) ? v.x : (j == 1) ? v.y : (j == 2) ? v.z : v.w;
                wsh[c * 128 + ((kc ^ (c & 7)) << 3) + ki] = __float2half(val);
            }
        }
    }
    __syncthreads();

    // ---- mma compute: acc[mi][ni][4], warp covers 32x32 ----
    float acc[2][4][4];
#pragma unroll
    for (int mi = 0; mi < 2; mi++)
#pragma unroll
        for (int ni = 0; ni < 4; ni++)
#pragma unroll
            for (int t = 0; t < 4; t++) acc[mi][ni][t] = 0.f;

    const unsigned xsb = (unsigned)__cvta_generic_to_shared(xs4);
    const unsigned wsb = (unsigned)__cvta_generic_to_shared(ws4);

#pragma unroll
    for (int kc = 0; kc < 8; kc++) {
        unsigned a[2][4];
#pragma unroll
        for (int mi = 0; mi < 2; mi++) {
            const int rl = wr + mi * 16 + (lane & 15);
            const int ch = kc * 2 + (lane >> 4);
            const unsigned ad = xsb + rl * 256 + ((ch ^ (rl & 7)) << 4);
            asm volatile("ldmatrix.sync.aligned.m8n8.x4.shared.b16 {%0,%1,%2,%3}, [%4];"
                         : "=r"(a[mi][0]), "=r"(a[mi][1]), "=r"(a[mi][2]), "=r"(a[mi][3])
                         : "r"(ad));
        }
        unsigned bf[4][2];
#pragma unroll
        for (int ni = 0; ni < 4; ni++) {
            const int cl = wc + ni * 8 + (lane & 7);
            const int ch = kc * 2 + ((lane >> 3) & 1);
            const unsigned ad = wsb + cl * 256 + ((ch ^ (cl & 7)) << 4);
            asm volatile("ldmatrix.sync.aligned.m8n8.x2.shared.b16 {%0,%1}, [%2];"
                         : "=r"(bf[ni][0]), "=r"(bf[ni][1])
                         : "r"(ad));
        }
#pragma unroll
        for (int mi = 0; mi < 2; mi++)
#pragma unroll
            for (int ni = 0; ni < 4; ni++)
                asm volatile("mma.sync.aligned.m16n8k16.row.col.f32.f16.f16.f32 "
                             "{%0,%1,%2,%3}, {%4,%5,%6,%7}, {%8,%9}, {%0,%1,%2,%3};"
                             : "+f"(acc[mi][ni][0]), "+f"(acc[mi][ni][1]),
                               "+f"(acc[mi][ni][2]), "+f"(acc[mi][ni][3])
                             : "r"(a[mi][0]), "r"(a[mi][1]), "r"(a[mi][2]), "r"(a[mi][3]),
                               "r"(bf[ni][0]), "r"(bf[ni][1]));
    }

    // ---- epilogue ----
    const int g   = lane >> 2;
    const int tig = lane & 3;
    if (ct < 4) {
        const int h = ct;
#pragma unroll
        for (int mi = 0; mi < 2; mi++) {
            const int lr1 = wr + mi * 16 + g;
            const int lr2 = lr1 + 8;
            float sS1 = 0.f, sT1 = 0.f, sS2 = 0.f, sT2 = 0.f;
#pragma unroll
            for (int ni = 0; ni < 4; ni++) {
                const int c0c = wc + ni * 8 + tig * 2;
                const float sv0 = score_src[h * FOUT + c0c];
                const float sv1 = score_src[h * FOUT + c0c + 1];
                const float tv0 = score_tgt[h * FOUT + c0c];
                const float tv1 = score_tgt[h * FOUT + c0c + 1];
                const float2 hi = {acc[mi][ni][0], acc[mi][ni][1]};
                const float2 lo = {acc[mi][ni][2], acc[mi][ni][3]};
                *(float2*)(g_h + ((size_t)h * N_NODES + r0 + lr1) * FOUT + c0c) = hi;
                *(float2*)(g_h + ((size_t)h * N_NODES + r0 + lr2) * FOUT + c0c) = lo;
                sS1 += hi.x * sv0 + hi.y * sv1;  sT1 += hi.x * tv0 + hi.y * tv1;
                sS2 += lo.x * sv0 + lo.y * sv1;  sT2 += lo.x * tv0 + lo.y * tv1;
            }
#pragma unroll
            for (int o = 1; o < 4; o <<= 1) {
                sS1 += __shfl_xor_sync(0xffffffffu, sS1, o);
                sT1 += __shfl_xor_sync(0xffffffffu, sT1, o);
                sS2 += __shfl_xor_sync(0xffffffffu, sS2, o);
                sT2 += __shfl_xor_sync(0xffffffffu, sT2, o);
            }
            if (tig == 0) {
                redS[w & 1][lr1] = sS1;  redT[w & 1][lr1] = sT1;
                redS[w & 1][lr2] = sS2;  redT[w & 1][lr2] = sT2;
            }
        }
        __syncthreads();
        if (tid < 64) {
            g_ss[(r0 + tid) * NH + h] = redS[0][tid] + redS[1][tid];
            g_st[(r0 + tid) * NH + h] = redT[0][tid] + redT[1][tid];
        }
    } else {
        const int c0g = (ct - 4) * 64;
#pragma unroll
        for (int mi = 0; mi < 2; mi++) {
            const int lr1 = wr + mi * 16 + g;
            const int lr2 = lr1 + 8;
#pragma unroll
            for (int ni = 0; ni < 4; ni++) {
                const int cc = c0g + wc + ni * 8 + tig * 2;
                const float2 hi = {acc[mi][ni][0], acc[mi][ni][1]};
                const float2 lo = {acc[mi][ni][2], acc[mi][ni][3]};
                *(float2*)(g_skip + (size_t)(r0 + lr1) * HF + cc) = hi;
                *(float2*)(g_skip + (size_t)(r0 + lr2) * HF + cc) = lo;
            }
        }
    }
}

// ============================================================
// Attention kernel (R7 structure): 128 threads/row, warp h owns
// head h. Fused score+exp+sum (no max). Gather unrolled x4.
// ============================================================
__global__ __launch_bounds__(128) void attn_kernel(
    const float* __restrict__ bias,
    float* __restrict__ out)
{
    const int n    = blockIdx.x;
    const int tid  = threadIdx.x;
    const int h    = tid >> 5;
    const int lane = tid & 31;

    __shared__ float2 pair[NH][MAXD];
    __shared__ float  partS[NH][NH + 1];

    const int deg = g_deg[n];
    const float4 ss4 = *(const float4*)(g_ss + (size_t)n * NH);
    const float4* st4 = (const float4*)g_st;
    const unsigned short* adj = g_adj + (size_t)n * MAXD;

    float s0 = 0.f, s1 = 0.f, s2 = 0.f, s3 = 0.f;
    for (int j = tid; j < deg; j += 128) {
        const int m = adj[j];
        const float4 st = st4[m];
        float v0 = ss4.x + st.x; v0 = v0 > 0.f ? v0 : 0.2f * v0;
        float v1 = ss4.y + st.y; v1 = v1 > 0.f ? v1 : 0.2f * v1;
        float v2 = ss4.z + st.z; v2 = v2 > 0.f ? v2 : 0.2f * v2;
        float v3 = ss4.w + st.w; v3 = v3 > 0.f ? v3 : 0.2f * v3;
        const float e0 = __expf(v0), e1 = __expf(v1);
        const float e2 = __expf(v2), e3 = __expf(v3);
        const float fo = __int_as_float(m * FOUT);
        pair[0][j] = make_float2(e0, fo);
        pair[1][j] = make_float2(e1, fo);
        pair[2][j] = make_float2(e2, fo);
        pair[3][j] = make_float2(e3, fo);
        s0 += e0; s1 += e1; s2 += e2; s3 += e3;
    }
#pragma unroll
    for (int o = 16; o; o >>= 1) {
        s0 += __shfl_xor_sync(0xffffffffu, s0, o);
        s1 += __shfl_xor_sync(0xffffffffu, s1, o);
        s2 += __shfl_xor_sync(0xffffffffu, s2, o);
        s3 += __shfl_xor_sync(0xffffffffu, s3, o);
    }
    if (lane == 0) {
        partS[h][0] = s0; partS[h][1] = s1;
        partS[h][2] = s2; partS[h][3] = s3;
    }
    __syncthreads();
    const float S = partS[0][h] + partS[1][h] + partS[2][h] + partS[3][h];

    const int g = lane >> 4;
    const int q = lane & 15;
    const float* hb = g_h + ((size_t)h * N_NODES) * FOUT + q * 4;
    float4 aA = {0.f, 0.f, 0.f, 0.f};
    float4 aB = {0.f, 0.f, 0.f, 0.f};
    int j = g;
    for (; j + 6 < deg; j += 8) {
        const float2 p0 = pair[h][j];
        const float2 p1 = pair[h][j + 2];
        const float2 p2 = pair[h][j + 4];
        const float2 p3 = pair[h][j + 6];
        const float4 v0 = *(const float4*)(hb + __float_as_int(p0.y));
        const float4 v1 = *(const float4*)(hb + __float_as_int(p1.y));
        const float4 v2 = *(const float4*)(hb + __float_as_int(p2.y));
        const float4 v3 = *(const float4*)(hb + __float_as_int(p3.y));
        aA.x = fmaf(p0.x, v0.x, aA.x); aA.y = fmaf(p0.x, v0.y, aA.y);
        aA.z = fmaf(p0.x, v0.z, aA.z); aA.w = fmaf(p0.x, v0.w, aA.w);
        aB.x = fmaf(p1.x, v1.x, aB.x); aB.y = fmaf(p1.x, v1.y, aB.y);
        aB.z = fmaf(p1.x, v1.z, aB.z); aB.w = fmaf(p1.x, v1.w, aB.w);
        aA.x = fmaf(p2.x, v2.x, aA.x); aA.y = fmaf(p2.x, v2.y, aA.y);
        aA.z = fmaf(p2.x, v2.z, aA.z); aA.w = fmaf(p2.x, v2.w, aA.w);
        aB.x = fmaf(p3.x, v3.x, aB.x); aB.y = fmaf(p3.x, v3.y, aB.y);
        aB.z = fmaf(p3.x, v3.z, aB.z); aB.w = fmaf(p3.x, v3.w, aB.w);
    }
    for (; j < deg; j += 2) {
        const float2 pr = pair[h][j];
        const float4 v  = *(const float4*)(hb + __float_as_int(pr.y));
        aA.x = fmaf(pr.x, v.x, aA.x); aA.y = fmaf(pr.x, v.y, aA.y);
        aA.z = fmaf(pr.x, v.z, aA.z); aA.w = fmaf(pr.x, v.w, aA.w);
    }
    float4 a = {aA.x + aB.x, aA.y + aB.y, aA.z + aB.z, aA.w + aB.w};
    a.x += __shfl_xor_sync(0xffffffffu, a.x, 16);
    a.y += __shfl_xor_sync(0xffffffffu, a.y, 16);
    a.z += __shfl_xor_sync(0xffffffffu, a.z, 16);
    a.w += __shfl_xor_sync(0xffffffffu, a.w, 16);

    if (g == 0) {
        const float inv = 1.f / S;
        const int c4 = h * 16 + q;
        const float4 sk = ((const float4*)(g_skip + (size_t)n * HF))[c4];
        const float4 bi = ((const float4*)bias)[c4];
        float o0 = a.x * inv + sk.x + bi.x;
        float o1 = a.y * inv + sk.y + bi.y;
        float o2 = a.z * inv + sk.z + bi.z;
        float o3 = a.w * inv + sk.w + bi.w;
        o0 = o0 > 0.f ? o0 : (__expf(o0) - 1.f);
        o1 = o1 > 0.f ? o1 : (__expf(o1) - 1.f);
        o2 = o2 > 0.f ? o2 : (__expf(o2) - 1.f);
        o3 = o3 > 0.f ? o3 : (__expf(o3) - 1.f);
        const float4 res = {o0, o1, o2, o3};
        ((float4*)(out + (size_t)n * HF))[c4] = res;
    }
}

// ============================================================
extern "C" void kernel_launch(void* const* d_in, const int* in_sizes, int n_in,
                              void* d_out, int out_size)
{
    const float* x         = (const float*)d_in[0];
    const float* mask      = (const float*)d_in[1];
    const float* proj      = (const float*)d_in[2];
    const float* score_src = (const float*)d_in[3];
    const float* score_tgt = (const float*)d_in[4];
    const float* skip_w    = (const float*)d_in[5];
    const float* bias      = (const float*)d_in[6];
    float* out             = (float*)d_out;

    prep_kernel<<<NBLK, 128>>>(x, mask, proj, score_src, score_tgt, skip_w);
    attn_kernel<<<N_NODES, 128>>>(bias, out);
}

// round 11
// speedup vs baseline: 1.2008x; 1.0257x over previous
#include <cuda_runtime.h>
#include <cuda_fp16.h>

#define N_NODES 4096
#define FIN     128
#define NH      4
#define FOUT    64
#define HF      256
#define MAXD    256
#define NBLK    1536   // b%3 in {0,1} -> scan (1024 blocks), b%3==2 -> GEMM (512)

// -------- device scratch --------
__device__ float g_h[NH * N_NODES * FOUT];       // fp32 [h][n][f] (4 MB)
__device__ float g_ss[N_NODES * NH];             // src score [n][h]
__device__ float g_st[N_NODES * NH];             // tgt score [n][h] (float4-loadable)
__device__ float g_skip[N_NODES * HF];           // skip proj result
__device__ unsigned short g_adj[(size_t)N_NODES * MAXD];
__device__ int   g_deg[N_NODES];

static __device__ __forceinline__ unsigned pack_half2(float a, float b) {
    const __half2 h = __floats2half2_rn(a, b);
    return *(const unsigned*)&h;
}

// ============================================================
// Fat kernel. b%3==2: tensor-core GEMM tile 64 rows x 64 cols of
// C[4096][512] (col-tiles 0..3 = proj heads + fused scores,
// 4..7 = skip). Else: mask scan, warp per row (4 rows/block).
// ============================================================
__global__ __launch_bounds__(128) void prep_kernel(
    const float* __restrict__ x,
    const float* __restrict__ mask,
    const float* __restrict__ proj,
    const float* __restrict__ score_src,
    const float* __restrict__ score_tgt,
    const float* __restrict__ skip_w)
{
    __shared__ uint4 xs4[64 * 16];   // A tile: 64 rows x 128 halves, swizzled (16 KB)
    __shared__ uint4 ws4[128 * 8];   // B tile: 16 KB (proj: [k=128][f=64]; skip: [c=64][k=128])
    __shared__ float redS[2][64], redT[2][64];

    const int b   = blockIdx.x;
    const int tid = threadIdx.x;

    if (b % 3 != 2) {
        // ---------------- scan role: warp per row ----------------
        const int sb   = (b / 3) * 2 + (b % 3);    // 0..1023
        const int wid  = tid >> 5;
        const int lane = tid & 31;
        const int row  = sb * 4 + wid;
        const float4* mr = (const float4*)(mask + (size_t)row * N_NODES);
        unsigned short* adj = g_adj + (size_t)row * MAXD;
        const unsigned lt = (1u << lane) - 1u;
        int base = 0;
#pragma unroll 16
        for (int g = 0; g < N_NODES / 128; g++) {
            const float4 v = mr[g * 32 + lane];
            const unsigned b0 = __ballot_sync(0xffffffffu, v.x == 0.f);
            const unsigned b1 = __ballot_sync(0xffffffffu, v.y == 0.f);
            const unsigned b2 = __ballot_sync(0xffffffffu, v.z == 0.f);
            const unsigned b3 = __ballot_sync(0xffffffffu, v.w == 0.f);
            const int c0 = __popc(b0), c1 = __popc(b1), c2 = __popc(b2), c3 = __popc(b3);
            const int e0 = g * 128 + lane * 4;
            if (v.x == 0.f) { int p = base + __popc(b0 & lt);                if (p < MAXD) adj[p] = (unsigned short)(e0);     }
            if (v.y == 0.f) { int p = base + c0 + __popc(b1 & lt);           if (p < MAXD) adj[p] = (unsigned short)(e0 + 1); }
            if (v.z == 0.f) { int p = base + c0 + c1 + __popc(b2 & lt);      if (p < MAXD) adj[p] = (unsigned short)(e0 + 2); }
            if (v.w == 0.f) { int p = base + c0 + c1 + c2 + __popc(b3 & lt); if (p < MAXD) adj[p] = (unsigned short)(e0 + 3); }
            base += c0 + c1 + c2 + c3;
        }
        if (lane == 0) g_deg[row] = min(base, MAXD);
        return;
    }

    // ---------------- GEMM role ----------------
    const int gb = b / 3;            // 0..511
    const int rt = gb >> 3;          // row tile 0..63
    const int ct = gb & 7;           // col tile 0..7
    const int r0 = rt * 64;
    const int w    = tid >> 5;       // warp 0..3
    const int lane = tid & 31;
    const int wr = (w >> 1) * 32;    // warp row offset in tile
    const int wc = (w & 1) * 32;     // warp col offset in tile

    // ---- stage A: x[r0..r0+64][0..128] fp32 -> fp16 swizzled [r][16 chunks] ----
    {
        const float4* xg = (const float4*)(x + (size_t)r0 * FIN);
#pragma unroll
        for (int i = 0; i < 8; i++) {
            const int idx = tid + i * 128;      // chunk 0..1023
            const int r = idx >> 4, c8 = idx & 15;
            const float4 v0 = xg[r * 32 + c8 * 2];
            const float4 v1 = xg[r * 32 + c8 * 2 + 1];
            uint4 pk;
            pk.x = pack_half2(v0.x, v0.y);
            pk.y = pack_half2(v0.z, v0.w);
            pk.z = pack_half2(v1.x, v1.y);
            pk.w = pack_half2(v1.z, v1.w);
            xs4[r * 16 + (c8 ^ (r & 7))] = pk;
        }
    }
    // ---- stage B ----
    if (ct >= 4) {
        // skip_w rows: [c=64][k=128] halves, 8 chunks/row... stored as 64 rows x 16 chunks
        // (row length 256B = 16 chunks) -> reuse same addressing as R10.
        const float4* wg = (const float4*)(skip_w + (size_t)((ct - 4) * 64) * FIN);
#pragma unroll
        for (int i = 0; i < 8; i++) {
            const int idx = tid + i * 128;
            const int r = idx >> 4, c8 = idx & 15;
            const float4 v0 = wg[r * 32 + c8 * 2];
            const float4 v1 = wg[r * 32 + c8 * 2 + 1];
            uint4 pk;
            pk.x = pack_half2(v0.x, v0.y);
            pk.y = pack_half2(v0.z, v0.w);
            pk.z = pack_half2(v1.x, v1.y);
            pk.w = pack_half2(v1.z, v1.w);
            ws4[r * 16 + (c8 ^ (r & 7))] = pk;
        }
    } else {
        // proj[ct] native [k=128][f=64]: 128 rows x 8 chunks, coalesced + conflict-free
        const float4* pg = (const float4*)(proj + (size_t)ct * FIN * FOUT);
#pragma unroll
        for (int i = 0; i < 8; i++) {
            const int idx = tid + i * 128;      // 0..1023
            const int r = idx >> 3, c8 = idx & 7;   // r = k row, c8 = f chunk
            const float4 v0 = pg[r * 16 + c8 * 2];
            const float4 v1 = pg[r * 16 + c8 * 2 + 1];
            uint4 pk;
            pk.x = pack_half2(v0.x, v0.y);
            pk.y = pack_half2(v0.z, v0.w);
            pk.z = pack_half2(v1.x, v1.y);
            pk.w = pack_half2(v1.z, v1.w);
            ws4[r * 8 + (c8 ^ (r & 7))] = pk;
        }
    }
    __syncthreads();

    // ---- mma compute ----
    float acc[2][4][4];
#pragma unroll
    for (int mi = 0; mi < 2; mi++)
#pragma unroll
        for (int ni = 0; ni < 4; ni++)
#pragma unroll
            for (int t = 0; t < 4; t++) acc[mi][ni][t] = 0.f;

    const unsigned xsb = (unsigned)__cvta_generic_to_shared(xs4);
    const unsigned wsb = (unsigned)__cvta_generic_to_shared(ws4);

#pragma unroll
    for (int kc = 0; kc < 8; kc++) {
        unsigned a[2][4];
#pragma unroll
        for (int mi = 0; mi < 2; mi++) {
            const int rl = wr + mi * 16 + (lane & 15);
            const int ch = kc * 2 + (lane >> 4);
            const unsigned ad = xsb + rl * 256 + ((ch ^ (rl & 7)) << 4);
            asm volatile("ldmatrix.sync.aligned.m8n8.x4.shared.b16 {%0,%1,%2,%3}, [%4];"
                         : "=r"(a[mi][0]), "=r"(a[mi][1]), "=r"(a[mi][2]), "=r"(a[mi][3])
                         : "r"(ad));
        }
        unsigned bf[4][2];
        if (ct >= 4) {
            // skip: B smem [c][k], non-trans x2 (proven in R10)
#pragma unroll
            for (int ni = 0; ni < 4; ni++) {
                const int cl = wc + ni * 8 + (lane & 7);
                const int ch = kc * 2 + ((lane >> 3) & 1);
                const unsigned ad = wsb + cl * 256 + ((ch ^ (cl & 7)) << 4);
                asm volatile("ldmatrix.sync.aligned.m8n8.x2.shared.b16 {%0,%1}, [%2];"
                             : "=r"(bf[ni][0]), "=r"(bf[ni][1])
                             : "r"(ad));
            }
        } else {
            // proj: B smem [k][f] (k-major), x2.trans — canonical B load
#pragma unroll
            for (int ni = 0; ni < 4; ni++) {
                const int k  = kc * 16 + (lane & 15);
                const int c8 = (wc >> 3) + ni;           // f chunk index
                const unsigned ad = wsb + (k * 8 + (c8 ^ (k & 7))) * 16;
                asm volatile("ldmatrix.sync.aligned.m8n8.x2.trans.shared.b16 {%0,%1}, [%2];"
                             : "=r"(bf[ni][0]), "=r"(bf[ni][1])
                             : "r"(ad));
            }
        }
#pragma unroll
        for (int mi = 0; mi < 2; mi++)
#pragma unroll
            for (int ni = 0; ni < 4; ni++)
                asm volatile("mma.sync.aligned.m16n8k16.row.col.f32.f16.f16.f32 "
                             "{%0,%1,%2,%3}, {%4,%5,%6,%7}, {%8,%9}, {%0,%1,%2,%3};"
                             : "+f"(acc[mi][ni][0]), "+f"(acc[mi][ni][1]),
                               "+f"(acc[mi][ni][2]), "+f"(acc[mi][ni][3])
                             : "r"(a[mi][0]), "r"(a[mi][1]), "r"(a[mi][2]), "r"(a[mi][3]),
                               "r"(bf[ni][0]), "r"(bf[ni][1]));
    }

    // ---- epilogue ----
    const int g   = lane >> 2;
    const int tig = lane & 3;
    if (ct < 4) {
        const int h = ct;
#pragma unroll
        for (int mi = 0; mi < 2; mi++) {
            const int lr1 = wr + mi * 16 + g;
            const int lr2 = lr1 + 8;
            float sS1 = 0.f, sT1 = 0.f, sS2 = 0.f, sT2 = 0.f;
#pragma unroll
            for (int ni = 0; ni < 4; ni++) {
                const int c0c = wc + ni * 8 + tig * 2;
                const float sv0 = score_src[h * FOUT + c0c];
                const float sv1 = score_src[h * FOUT + c0c + 1];
                const float tv0 = score_tgt[h * FOUT + c0c];
                const float tv1 = score_tgt[h * FOUT + c0c + 1];
                const float2 hi = {acc[mi][ni][0], acc[mi][ni][1]};
                const float2 lo = {acc[mi][ni][2], acc[mi][ni][3]};
                *(float2*)(g_h + ((size_t)h * N_NODES + r0 + lr1) * FOUT + c0c) = hi;
                *(float2*)(g_h + ((size_t)h * N_NODES + r0 + lr2) * FOUT + c0c) = lo;
                sS1 += hi.x * sv0 + hi.y * sv1;  sT1 += hi.x * tv0 + hi.y * tv1;
                sS2 += lo.x * sv0 + lo.y * sv1;  sT2 += lo.x * tv0 + lo.y * tv1;
            }
#pragma unroll
            for (int o = 1; o < 4; o <<= 1) {
                sS1 += __shfl_xor_sync(0xffffffffu, sS1, o);
                sT1 += __shfl_xor_sync(0xffffffffu, sT1, o);
                sS2 += __shfl_xor_sync(0xffffffffu, sS2, o);
                sT2 += __shfl_xor_sync(0xffffffffu, sT2, o);
            }
            if (tig == 0) {
                redS[w & 1][lr1] = sS1;  redT[w & 1][lr1] = sT1;
                redS[w & 1][lr2] = sS2;  redT[w & 1][lr2] = sT2;
            }
        }
        __syncthreads();
        if (tid < 64) {
            g_ss[(r0 + tid) * NH + h] = redS[0][tid] + redS[1][tid];
            g_st[(r0 + tid) * NH + h] = redT[0][tid] + redT[1][tid];
        }
    } else {
        const int c0g = (ct - 4) * 64;
#pragma unroll
        for (int mi = 0; mi < 2; mi++) {
            const int lr1 = wr + mi * 16 + g;
            const int lr2 = lr1 + 8;
#pragma unroll
            for (int ni = 0; ni < 4; ni++) {
                const int cc = c0g + wc + ni * 8 + tig * 2;
                const float2 hi = {acc[mi][ni][0], acc[mi][ni][1]};
                const float2 lo = {acc[mi][ni][2], acc[mi][ni][3]};
                *(float2*)(g_skip + (size_t)(r0 + lr1) * HF + cc) = hi;
                *(float2*)(g_skip + (size_t)(r0 + lr2) * HF + cc) = lo;
            }
        }
    }
}

// ============================================================
// Attention: 256 threads/row. Warps 0-3 = heads (half 0),
// warps 4-7 = heads (half 1). 4 j-subgroups per head (stride 4).
// Score phase is a single shot (deg <= 256). Two barriers total.
// ============================================================
__global__ __launch_bounds__(256) void attn_kernel(
    const float* __restrict__ bias,
    float* __restrict__ out)
{
    const int n    = blockIdx.x;
    const int tid  = threadIdx.x;
    const int wid  = tid >> 5;
    const int lane = tid & 31;
    const int h    = wid & 3;
    const int half = wid >> 2;

    __shared__ float2 pair[NH][MAXD];     // 8 KB
    __shared__ float  partS[8][NH];
    __shared__ float4 accH[NH][16];       // half-1 partials (4 KB)

    const int deg = g_deg[n];
    const unsigned short* adj = g_adj + (size_t)n * MAXD;
    const float4 ss4 = *(const float4*)(g_ss + (size_t)n * NH);
    const float4* st4 = (const float4*)g_st;

    // ---- score phase: one shot ----
    float s0 = 0.f, s1 = 0.f, s2 = 0.f, s3 = 0.f;
    if (tid < deg) {
        const int m = adj[tid];
        const float4 st = st4[m];
        float v0 = ss4.x + st.x; v0 = v0 > 0.f ? v0 : 0.2f * v0;
        float v1 = ss4.y + st.y; v1 = v1 > 0.f ? v1 : 0.2f * v1;
        float v2 = ss4.z + st.z; v2 = v2 > 0.f ? v2 : 0.2f * v2;
        float v3 = ss4.w + st.w; v3 = v3 > 0.f ? v3 : 0.2f * v3;
        s0 = __expf(v0); s1 = __expf(v1); s2 = __expf(v2); s3 = __expf(v3);
        const float fo = __int_as_float(m * FOUT);
        pair[0][tid] = make_float2(s0, fo);
        pair[1][tid] = make_float2(s1, fo);
        pair[2][tid] = make_float2(s2, fo);
        pair[3][tid] = make_float2(s3, fo);
    }
#pragma unroll
    for (int o = 16; o; o >>= 1) {
        s0 += __shfl_xor_sync(0xffffffffu, s0, o);
        s1 += __shfl_xor_sync(0xffffffffu, s1, o);
        s2 += __shfl_xor_sync(0xffffffffu, s2, o);
        s3 += __shfl_xor_sync(0xffffffffu, s3, o);
    }
    if (lane == 0) {
        partS[wid][0] = s0; partS[wid][1] = s1;
        partS[wid][2] = s2; partS[wid][3] = s3;
    }
    __syncthreads();
    const float S = partS[0][h] + partS[1][h] + partS[2][h] + partS[3][h] +
                    partS[4][h] + partS[5][h] + partS[6][h] + partS[7][h];

    // ---- gather: subgroup sg handles j = sg, sg+4, ... ----
    const int sg = half * 2 + (lane >> 4);
    const int q  = lane & 15;
    const float* hb = g_h + ((size_t)h * N_NODES) * FOUT + q * 4;
    float4 aA = {0.f, 0.f, 0.f, 0.f};
    float4 aB = {0.f, 0.f, 0.f, 0.f};
    int j = sg;
    for (; j + 12 < deg; j += 16) {
        const float2 p0 = pair[h][j];
        const float2 p1 = pair[h][j + 4];
        const float2 p2 = pair[h][j + 8];
        const float2 p3 = pair[h][j + 12];
        const float4 v0 = *(const float4*)(hb + __float_as_int(p0.y));
        const float4 v1 = *(const float4*)(hb + __float_as_int(p1.y));
        const float4 v2 = *(const float4*)(hb + __float_as_int(p2.y));
        const float4 v3 = *(const float4*)(hb + __float_as_int(p3.y));
        aA.x = fmaf(p0.x, v0.x, aA.x); aA.y = fmaf(p0.x, v0.y, aA.y);
        aA.z = fmaf(p0.x, v0.z, aA.z); aA.w = fmaf(p0.x, v0.w, aA.w);
        aB.x = fmaf(p1.x, v1.x, aB.x); aB.y = fmaf(p1.x, v1.y, aB.y);
        aB.z = fmaf(p1.x, v1.z, aB.z); aB.w = fmaf(p1.x, v1.w, aB.w);
        aA.x = fmaf(p2.x, v2.x, aA.x); aA.y = fmaf(p2.x, v2.y, aA.y);
        aA.z = fmaf(p2.x, v2.z, aA.z); aA.w = fmaf(p2.x, v2.w, aA.w);
        aB.x = fmaf(p3.x, v3.x, aB.x); aB.y = fmaf(p3.x, v3.y, aB.y);
        aB.z = fmaf(p3.x, v3.z, aB.z); aB.w = fmaf(p3.x, v3.w, aB.w);
    }
    for (; j < deg; j += 4) {
        const float2 pr = pair[h][j];
        const float4 v  = *(const float4*)(hb + __float_as_int(pr.y));
        aA.x = fmaf(pr.x, v.x, aA.x); aA.y = fmaf(pr.x, v.y, aA.y);
        aA.z = fmaf(pr.x, v.z, aA.z); aA.w = fmaf(pr.x, v.w, aA.w);
    }
    float4 a = {aA.x + aB.x, aA.y + aB.y, aA.z + aB.z, aA.w + aB.w};
    a.x += __shfl_xor_sync(0xffffffffu, a.x, 16);
    a.y += __shfl_xor_sync(0xffffffffu, a.y, 16);
    a.z += __shfl_xor_sync(0xffffffffu, a.z, 16);
    a.w += __shfl_xor_sync(0xffffffffu, a.w, 16);

    if (half == 1 && lane < 16) accH[h][q] = a;
    __syncthreads();

    if (half == 0 && lane < 16) {
        const float4 o2 = accH[h][q];
        const float inv = 1.f / S;
        const int c4 = h * 16 + q;
        const float4 sk = ((const float4*)(g_skip + (size_t)n * HF))[c4];
        const float4 bi = ((const float4*)bias)[c4];
        float o0 = (a.x + o2.x) * inv + sk.x + bi.x;
        float o1 = (a.y + o2.y) * inv + sk.y + bi.y;
        float o2v = (a.z + o2.z) * inv + sk.z + bi.z;
        float o3 = (a.w + o2.w) * inv + sk.w + bi.w;
        o0  = o0  > 0.f ? o0  : (__expf(o0)  - 1.f);
        o1  = o1  > 0.f ? o1  : (__expf(o1)  - 1.f);
        o2v = o2v > 0.f ? o2v : (__expf(o2v) - 1.f);
        o3  = o3  > 0.f ? o3  : (__expf(o3)  - 1.f);
        const float4 res = {o0, o1, o2v, o3};
        ((float4*)(out + (size_t)n * HF))[c4] = res;
    }
}

// ============================================================
extern "C" void kernel_launch(void* const* d_in, const int* in_sizes, int n_in,
                              void* d_out, int out_size)
{
    const float* x         = (const float*)d_in[0];
    const float* mask      = (const float*)d_in[1];
    const float* proj      = (const float*)d_in[2];
    const float* score_src = (const float*)d_in[3];
    const float* score_tgt = (const float*)d_in[4];
    const float* skip_w    = (const float*)d_in[5];
    const float* bias      = (const float*)d_in[6];
    float* out             = (float*)d_out;

    prep_kernel<<<NBLK, 128>>>(x, mask, proj, score_src, score_tgt, skip_w);
    attn_kernel<<<N_NODES, 256>>>(bias, out);
}